// round 13
// baseline (speedup 1.0000x reference)
#include <cuda_runtime.h>
#include <cuda_fp16.h>
#include <cstdint>
#include <cstddef>

// Problem constants: B=64, S=128, D_MODEL=1024, D_INNER=1024
#define M_TOT 8192
#define KDIM  1024
#define NDIM  1024

// Scratch (allowed: __device__ globals)
__device__ __align__(16) __half g_emb_h[(size_t)M_TOT * KDIM]; // fp16 embeddings
__device__ __align__(16) __half g_wq_t[(size_t)KDIM * NDIM];   // Wq^T fp16 [N][K]
__device__ __align__(16) __half g_wv_t[(size_t)KDIM * NDIM];   // Wv^T fp16
__device__ __align__(16) __half g_wo_t[(size_t)KDIM * NDIM];   // Wo^T fp16
__device__ __align__(16) __half g_mid[(size_t)M_TOT * NDIM];   // g = fp16(sigmoid(q)*v)

// ---------------------------------------------------------------------------
// helpers
// ---------------------------------------------------------------------------
__device__ __forceinline__ uint32_t h2u(__half2 h) {
    return *reinterpret_cast<uint32_t*>(&h);
}

__device__ __forceinline__ void cp16(uint32_t saddr, const void* gptr) {
    asm volatile("cp.async.cg.shared.global [%0], [%1], 16;" :: "r"(saddr), "l"(gptr));
}

__device__ __forceinline__ void ldsm4(uint32_t r[4], uint32_t saddr) {
    asm volatile("ldmatrix.sync.aligned.m8n8.x4.shared.b16 {%0,%1,%2,%3}, [%4];"
                 : "=r"(r[0]), "=r"(r[1]), "=r"(r[2]), "=r"(r[3]) : "r"(saddr));
}

// fp16 mma, fp32 accumulate: C(16x8) += A(16x16) @ B(16x8)
__device__ __forceinline__ void mma_f16(float c[4], const uint32_t a[4],
                                        uint32_t b0, uint32_t b1) {
    asm volatile(
        "mma.sync.aligned.m16n8k16.row.col.f32.f16.f16.f32 "
        "{%0,%1,%2,%3},{%4,%5,%6,%7},{%8,%9},{%0,%1,%2,%3};"
        : "+f"(c[0]), "+f"(c[1]), "+f"(c[2]), "+f"(c[3])
        : "r"(a[0]), "r"(a[1]), "r"(a[2]), "r"(a[3]), "r"(b0), "r"(b1));
}

__device__ __forceinline__ float sigmf(float x) {
    return 1.0f / (1.0f + __expf(-x));
}

// ---------------------------------------------------------------------------
// Merged prepass: one launch does fp32->fp16 of emb (blocks 0..4095) and
// transpose+convert of the 3 live weight matrices (blocks 4096..7167).
// ---------------------------------------------------------------------------
__global__ void prep_kernel(const float* __restrict__ emb,
                            const float* __restrict__ Wq,
                            const float* __restrict__ Wv,
                            const float* __restrict__ Wo,
                            __half* __restrict__ embh,
                            __half* __restrict__ wqt,
                            __half* __restrict__ wvt,
                            __half* __restrict__ wot) {
    __shared__ float tile[32][33];
    const int bx = blockIdx.x;
    const int tid = threadIdx.x;

    if (bx < 4096) {
        // f2h: 8M halfs = 1M uint4 chunks, one per thread
        const int i = bx * 256 + tid;
        const float4* in = reinterpret_cast<const float4*>(emb);
        uint4* out = reinterpret_cast<uint4*>(embh);
        float4 a = in[2 * i], b = in[2 * i + 1];
        uint4 o;
        o.x = h2u(__float22half2_rn(make_float2(a.x, a.y)));
        o.y = h2u(__float22half2_rn(make_float2(a.z, a.w)));
        o.z = h2u(__float22half2_rn(make_float2(b.x, b.y)));
        o.w = h2u(__float22half2_rn(make_float2(b.z, b.w)));
        out[i] = o;
    } else {
        // transpose+convert: out[n][k] = fp16(in[k][n]) for one 1024x1024 matrix
        const int t = bx - 4096;
        const int mat = t >> 10;              // 0,1,2
        const int tt = t & 1023;
        const float* in = (mat == 0) ? Wq : (mat == 1) ? Wv : Wo;
        __half* out = (mat == 0) ? wqt : (mat == 1) ? wvt : wot;
        const int bn = (tt & 31) * 32;        // n-block
        const int bk = (tt >> 5) * 32;        // k-block
        const int tx = tid & 31, ty = tid >> 5;
#pragma unroll
        for (int j = 0; j < 4; j++)
            tile[ty + j * 8][tx] = in[(size_t)(bk + ty + j * 8) * NDIM + bn + tx];
        __syncthreads();
#pragma unroll
        for (int j = 0; j < 4; j++)
            out[(size_t)(bn + ty + j * 8) * KDIM + bk + tx] =
                __float2half_rn(tile[tx][ty + j * 8]);
    }
}

// ---------------------------------------------------------------------------
// FP16 tensor-core GEMM (fp32 accum), BK=32, PITCH=80B rows (conflict-free),
// 4-stage cp.async ring. Warp grid WMW x (NWARP/WMW).
//   DUAL=true : Ch = fp16( sigmoid(A@B0^T + bias0) * (A@B1^T + bias1) )
//   DUAL=false: Cf = A@B0^T + bias0
// A: [M][K] fp16 row-major.  Bt*: [N][K] fp16 row-major (pre-transposed).
// ---------------------------------------------------------------------------
template <bool DUAL, int BM, int BN, int WMW, int THREADS>
__global__ __launch_bounds__(THREADS, 2)
void gemm_f16(const __half* __restrict__ A, const __half* __restrict__ Bt0,
              const __half* __restrict__ Bt1, const float* __restrict__ bias0,
              const float* __restrict__ bias1, void* __restrict__ Cv) {
    constexpr int BK = 32, NSTAGE = 4;
    constexpr int NWARP = THREADS / 32;
    constexpr int WNW = NWARP / WMW;           // warps along n
    constexpr int WM = BM / WMW;
    constexpr int WN = BN / WNW;
    constexpr int MT = WM / 16;                // m16 tiles per warp
    constexpr int NT = WN / 8;                 // n8 tiles per warp
    constexpr int PITCH = 80;                  // BK*2=64B + 16B pad (bank-disjoint)
    constexpr int A_BYTES = BM * PITCH;
    constexpr int B_BYTES = BN * PITCH;
    constexpr int NB = DUAL ? 2 : 1;
    constexpr int STAGE = A_BYTES + B_BYTES * NB;
    constexpr int KT = KDIM / BK;              // 32
    constexpr int ALD = BM * 4 / THREADS;
    constexpr int BLD = BN * 4 / THREADS;
    constexpr int OFF_BIAS = NSTAGE * STAGE;

    extern __shared__ char smem[];
    const int tid  = threadIdx.x;
    const int lane = tid & 31, warp = tid >> 5;
    const int wm = warp / WNW, wn = warp % WNW;
    const int mBase = blockIdx.y * BM, nBase = blockIdx.x * BN;

    const uint32_t sBase = (uint32_t)__cvta_generic_to_shared(smem);

    {   // stage biases into smem for the epilogue
        float* bsw = reinterpret_cast<float*>(smem + OFF_BIAS);
        for (int i = tid; i < BN; i += THREADS) {
            bsw[i] = bias0[nBase + i];
            if constexpr (DUAL) bsw[BN + i] = bias1[nBase + i];
        }
    }

    // lane-dependent ldmatrix source offsets (bytes within a stage).
    const int lt = lane >> 3, lr = lane & 7;
    const uint32_t aOff = (uint32_t)((wm * WM + (lt & 1) * 8 + lr) * PITCH + (lt >> 1) * 16);
    const uint32_t bOff = (uint32_t)(A_BYTES + (wn * WN + (lt >> 1) * 8 + lr) * PITCH + (lt & 1) * 16);

    auto load_stage = [&](int st, int k0) {   // k0 in halfs
        const uint32_t sb = sBase + st * STAGE;
#pragma unroll
        for (int i = 0; i < ALD; i++) {
            const int ch = tid + i * THREADS;
            const int row = ch >> 2, kc = ch & 3;           // 4 x 16B chunks per row
            cp16(sb + row * PITCH + kc * 16,
                 A + (size_t)(mBase + row) * KDIM + k0 + kc * 8);
        }
#pragma unroll
        for (int i = 0; i < BLD; i++) {
            const int ch = tid + i * THREADS;
            const int row = ch >> 2, kc = ch & 3;
            const size_t g = (size_t)(nBase + row) * KDIM + k0 + kc * 8;
            const uint32_t sa = sb + A_BYTES + row * PITCH + kc * 16;
            cp16(sa, Bt0 + g);
            if constexpr (DUAL) cp16(sa + B_BYTES, Bt1 + g);
        }
    };

    float acc0[MT][NT][4];
    float acc1[DUAL ? MT : 1][DUAL ? NT : 1][4];
#pragma unroll
    for (int mt = 0; mt < MT; mt++)
#pragma unroll
        for (int nt = 0; nt < NT; nt++)
#pragma unroll
            for (int i = 0; i < 4; i++) {
                acc0[mt][nt][i] = 0.0f;
                if constexpr (DUAL) acc1[mt][nt][i] = 0.0f;
            }

#pragma unroll
    for (int st = 0; st < NSTAGE - 1; st++) {
        load_stage(st, st * BK);
        asm volatile("cp.async.commit_group;");
    }

#pragma unroll 1
    for (int kt = 0; kt < KT; kt++) {
        const int cmp_st = kt & (NSTAGE - 1);
        asm volatile("cp.async.wait_group 2;");
        __syncthreads();

        if (kt + NSTAGE - 1 < KT)
            load_stage((kt + NSTAGE - 1) & (NSTAGE - 1), (kt + NSTAGE - 1) * BK);
        asm volatile("cp.async.commit_group;");

        const uint32_t sb = sBase + cmp_st * STAGE;
#pragma unroll
        for (int kk = 0; kk < 2; kk++) {               // 2 x k16 per BK=32 stage
            uint32_t a[MT][4];
#pragma unroll
            for (int mt = 0; mt < MT; mt++)
                ldsm4(a[mt], sb + aOff + mt * 16 * PITCH + kk * 32);

            uint32_t b[NT / 2][4];
#pragma unroll
            for (int np = 0; np < NT / 2; np++)
                ldsm4(b[np], sb + bOff + np * 16 * PITCH + kk * 32);
#pragma unroll
            for (int mt = 0; mt < MT; mt++)
#pragma unroll
                for (int nt = 0; nt < NT; nt++)
                    mma_f16(acc0[mt][nt], a[mt],
                            b[nt >> 1][(nt & 1) * 2], b[nt >> 1][(nt & 1) * 2 + 1]);

            if constexpr (DUAL) {
#pragma unroll
                for (int np = 0; np < NT / 2; np++)
                    ldsm4(b[np], sb + bOff + B_BYTES + np * 16 * PITCH + kk * 32);
#pragma unroll
                for (int mt = 0; mt < MT; mt++)
#pragma unroll
                    for (int nt = 0; nt < NT; nt++)
                        mma_f16(acc1[mt][nt], a[mt],
                                b[nt >> 1][(nt & 1) * 2], b[nt >> 1][(nt & 1) * 2 + 1]);
            }
        }
    }

    // epilogue: c0,c1 at (row g, cols 2t,2t+1); c2,c3 at row g+8
    const float* bsr = reinterpret_cast<const float*>(smem + OFF_BIAS);
    const int r0b = mBase + wm * WM + (lane >> 2);
    const int cbl = wn * WN + (lane & 3) * 2;   // column within block tile
#pragma unroll
    for (int mt = 0; mt < MT; mt++) {
#pragma unroll
        for (int nt = 0; nt < NT; nt++) {
            const int cl = cbl + nt * 8;        // local col
            const int c  = nBase + cl;          // global col
            const int r0 = r0b + mt * 16;
            const int r1 = r0 + 8;
            if constexpr (DUAL) {
                __half* C = reinterpret_cast<__half*>(Cv);
                const float bq0 = bsr[cl], bq1 = bsr[cl + 1];
                const float bv0 = bsr[BN + cl], bv1 = bsr[BN + cl + 1];
                const float g00 = (acc1[mt][nt][0] + bv0) * sigmf(acc0[mt][nt][0] + bq0);
                const float g01 = (acc1[mt][nt][1] + bv1) * sigmf(acc0[mt][nt][1] + bq1);
                const float g10 = (acc1[mt][nt][2] + bv0) * sigmf(acc0[mt][nt][2] + bq0);
                const float g11 = (acc1[mt][nt][3] + bv1) * sigmf(acc0[mt][nt][3] + bq1);
                *reinterpret_cast<__half2*>(C + (size_t)r0 * NDIM + c) =
                    __float22half2_rn(make_float2(g00, g01));
                *reinterpret_cast<__half2*>(C + (size_t)r1 * NDIM + c) =
                    __float22half2_rn(make_float2(g10, g11));
            } else {
                float* C = reinterpret_cast<float*>(Cv);
                const float b0v = bsr[cl], b1v = bsr[cl + 1];
                *reinterpret_cast<float2*>(C + (size_t)r0 * NDIM + c) =
                    make_float2(acc0[mt][nt][0] + b0v, acc0[mt][nt][1] + b1v);
                *reinterpret_cast<float2*>(C + (size_t)r1 * NDIM + c) =
                    make_float2(acc0[mt][nt][2] + b0v, acc0[mt][nt][3] + b1v);
            }
        }
    }
}

// ---------------------------------------------------------------------------
// launch
// ---------------------------------------------------------------------------
extern "C" void kernel_launch(void* const* d_in, const int* in_sizes, int n_in,
                              void* d_out, int out_size) {
    (void)in_sizes; (void)n_in; (void)out_size;
    const float* emb = (const float*)d_in[0];
    const float* Wq  = (const float*)d_in[1];
    const float* bq  = (const float*)d_in[2];
    // d_in[3]=Wk, d_in[4]=bk, d_in[7]=w: algebraically dead (num/den cancels to v)
    const float* Wv  = (const float*)d_in[5];
    const float* bv  = (const float*)d_in[6];
    const float* Wo  = (const float*)d_in[8];
    const float* bo  = (const float*)d_in[9];
    float* out = (float*)d_out;

    __half *embh, *wqt, *wvt, *wot, *mid;
    cudaGetSymbolAddress((void**)&embh, g_emb_h);
    cudaGetSymbolAddress((void**)&wqt,  g_wq_t);
    cudaGetSymbolAddress((void**)&wvt,  g_wv_t);
    cudaGetSymbolAddress((void**)&wot,  g_wo_t);
    cudaGetSymbolAddress((void**)&mid,  g_mid);

    // G1: BM=64 BN=64 dual, 256thr, warp grid 2m x 4n. Real need: 4*15360+512.
    // Padded to 78336 to pin exactly 2 CTAs/SM (3 resident would give worse
    // wave quantization: 2048/444 -> 5 waves @ 92% vs 2048/296 -> 7 @ 98.8%).
    constexpr int SMEM1 = 78336;
    // G2: BM=128 BN=128 single, 256thr, warp grid 4m x 2n (R12 geometry).
    constexpr int SMEM2 = 4 * 20480 + 1024;   // 82944 -> 2 CTAs/SM
    cudaFuncSetAttribute((const void*)gemm_f16<true, 64, 64, 2, 256>,
                         cudaFuncAttributeMaxDynamicSharedMemorySize, SMEM1);
    cudaFuncSetAttribute((const void*)gemm_f16<false, 128, 128, 4, 256>,
                         cudaFuncAttributeMaxDynamicSharedMemorySize, SMEM2);

    // merged prepass: 1 launch (f2h emb + 3 weight transposes, concurrent)
    prep_kernel<<<7168, 256>>>(emb, Wq, Wv, Wo, embh, wqt, wvt, wot);

    // g = fp16( sigmoid(emb@Wq + bq) * (emb@Wv + bv) )
    dim3 g1(NDIM / 64, M_TOT / 64);    // (16, 128) = 2048 CTAs -> 6.92 waves
    gemm_f16<true, 64, 64, 2, 256><<<g1, 256, SMEM1>>>(embh, wqt, wvt, bq, bv, (void*)mid);

    // out = g @ Wo + bo
    dim3 g2(NDIM / 128, M_TOT / 128);  // (8, 64) = 512 CTAs
    gemm_f16<false, 128, 128, 4, 256><<<g2, 256, SMEM2>>>(mid, wot, nullptr, bo, nullptr, (void*)out);
}

// round 14
// speedup vs baseline: 1.1552x; 1.1552x over previous
#include <cuda_runtime.h>
#include <cuda_fp16.h>
#include <cstdint>
#include <cstddef>

// Problem constants: B=64, S=128, D_MODEL=1024, D_INNER=1024
#define M_TOT 8192
#define KDIM  1024
#define NDIM  1024

// Scratch (allowed: __device__ globals)
__device__ __align__(16) __half g_emb_h[(size_t)M_TOT * KDIM]; // fp16 embeddings
__device__ __align__(16) __half g_wq_t[(size_t)KDIM * NDIM];   // Wq^T fp16 [N][K]
__device__ __align__(16) __half g_wv_t[(size_t)KDIM * NDIM];   // Wv^T fp16
__device__ __align__(16) __half g_wo_t[(size_t)KDIM * NDIM];   // Wo^T fp16
__device__ __align__(16) __half g_mid[(size_t)M_TOT * NDIM];   // g = fp16(sigmoid(q)*v)

// ---------------------------------------------------------------------------
// helpers
// ---------------------------------------------------------------------------
__device__ __forceinline__ uint32_t h2u(__half2 h) {
    return *reinterpret_cast<uint32_t*>(&h);
}

__device__ __forceinline__ void cp16(uint32_t saddr, const void* gptr) {
    asm volatile("cp.async.cg.shared.global [%0], [%1], 16;" :: "r"(saddr), "l"(gptr));
}

__device__ __forceinline__ void ldsm4(uint32_t r[4], uint32_t saddr) {
    asm volatile("ldmatrix.sync.aligned.m8n8.x4.shared.b16 {%0,%1,%2,%3}, [%4];"
                 : "=r"(r[0]), "=r"(r[1]), "=r"(r[2]), "=r"(r[3]) : "r"(saddr));
}

// fp16 mma, fp32 accumulate: C(16x8) += A(16x16) @ B(16x8)
__device__ __forceinline__ void mma_f16(float c[4], const uint32_t a[4],
                                        uint32_t b0, uint32_t b1) {
    asm volatile(
        "mma.sync.aligned.m16n8k16.row.col.f32.f16.f16.f32 "
        "{%0,%1,%2,%3},{%4,%5,%6,%7},{%8,%9},{%0,%1,%2,%3};"
        : "+f"(c[0]), "+f"(c[1]), "+f"(c[2]), "+f"(c[3])
        : "r"(a[0]), "r"(a[1]), "r"(a[2]), "r"(a[3]), "r"(b0), "r"(b1));
}

__device__ __forceinline__ float sigmf(float x) {
    return 1.0f / (1.0f + __expf(-x));
}

// ---------------------------------------------------------------------------
// Merged prepass: one launch does fp32->fp16 of emb (blocks 0..4095) and
// transpose+convert of the 3 live weight matrices (blocks 4096..7167).
// ---------------------------------------------------------------------------
__global__ void prep_kernel(const float* __restrict__ emb,
                            const float* __restrict__ Wq,
                            const float* __restrict__ Wv,
                            const float* __restrict__ Wo,
                            __half* __restrict__ embh,
                            __half* __restrict__ wqt,
                            __half* __restrict__ wvt,
                            __half* __restrict__ wot) {
    __shared__ float tile[32][33];
    const int bx = blockIdx.x;
    const int tid = threadIdx.x;

    if (bx < 4096) {
        // f2h: 8M halfs = 1M uint4 chunks, one per thread
        const int i = bx * 256 + tid;
        const float4* in = reinterpret_cast<const float4*>(emb);
        uint4* out = reinterpret_cast<uint4*>(embh);
        float4 a = in[2 * i], b = in[2 * i + 1];
        uint4 o;
        o.x = h2u(__float22half2_rn(make_float2(a.x, a.y)));
        o.y = h2u(__float22half2_rn(make_float2(a.z, a.w)));
        o.z = h2u(__float22half2_rn(make_float2(b.x, b.y)));
        o.w = h2u(__float22half2_rn(make_float2(b.z, b.w)));
        out[i] = o;
    } else {
        // transpose+convert: out[n][k] = fp16(in[k][n]) for one 1024x1024 matrix
        const int t = bx - 4096;
        const int mat = t >> 10;              // 0,1,2
        const int tt = t & 1023;
        const float* in = (mat == 0) ? Wq : (mat == 1) ? Wv : Wo;
        __half* out = (mat == 0) ? wqt : (mat == 1) ? wvt : wot;
        const int bn = (tt & 31) * 32;        // n-block
        const int bk = (tt >> 5) * 32;        // k-block
        const int tx = tid & 31, ty = tid >> 5;
#pragma unroll
        for (int j = 0; j < 4; j++)
            tile[ty + j * 8][tx] = in[(size_t)(bk + ty + j * 8) * NDIM + bn + tx];
        __syncthreads();
#pragma unroll
        for (int j = 0; j < 4; j++)
            out[(size_t)(bn + ty + j * 8) * KDIM + bk + tx] =
                __float2half_rn(tile[tx][ty + j * 8]);
    }
}

// ---------------------------------------------------------------------------
// FP16 tensor-core GEMM (fp32 accum), BK=32, PITCH=80B rows (conflict-free),
// 4-stage cp.async ring. 128 threads = 4 warps in a 2m x 2n grid
// (minimizes LDSM operand duplication: A dup = 2, B dup = 2).
//   DUAL=true : BM=128, BN=64 : Ch = fp16( sigmoid(A@B0^T+b0) * (A@B1^T+b1) )
//   DUAL=false: BM=128, BN=128: Cf = A@B0^T + b0
// A: [M][K] fp16 row-major.  Bt*: [N][K] fp16 row-major (pre-transposed).
// ---------------------------------------------------------------------------
template <bool DUAL, int BM, int BN>
__global__ __launch_bounds__(128, 2)
void gemm_f16(const __half* __restrict__ A, const __half* __restrict__ Bt0,
              const __half* __restrict__ Bt1, const float* __restrict__ bias0,
              const float* __restrict__ bias1, void* __restrict__ Cv) {
    constexpr int BK = 32, NSTAGE = 4, THREADS = 128;
    constexpr int WMW = 2, WNW = 2;            // 4-warp grid
    constexpr int WM = BM / WMW;               // 64
    constexpr int WN = BN / WNW;               // 32 (dual) / 64 (single)
    constexpr int MT = WM / 16;                // 4
    constexpr int NT = WN / 8;                 // 4 / 8
    constexpr int PITCH = 80;                  // BK*2=64B + 16B pad (bank-disjoint)
    constexpr int A_BYTES = BM * PITCH;
    constexpr int B_BYTES = BN * PITCH;
    constexpr int NB = DUAL ? 2 : 1;
    constexpr int STAGE = A_BYTES + B_BYTES * NB;   // 20480 both variants
    constexpr int KT = KDIM / BK;              // 32
    constexpr int ALD = BM * 4 / THREADS;      // 4
    constexpr int BLD = BN * 4 / THREADS;      // 2 (dual) / 4 (single)
    constexpr int OFF_BIAS = NSTAGE * STAGE;

    extern __shared__ char smem[];
    const int tid  = threadIdx.x;
    const int lane = tid & 31, warp = tid >> 5;
    const int wm = warp >> 1, wn = warp & 1;
    const int mBase = blockIdx.y * BM, nBase = blockIdx.x * BN;

    const uint32_t sBase = (uint32_t)__cvta_generic_to_shared(smem);

    {   // stage biases into smem for the epilogue
        float* bsw = reinterpret_cast<float*>(smem + OFF_BIAS);
        for (int i = tid; i < BN; i += THREADS) {
            bsw[i] = bias0[nBase + i];
            if constexpr (DUAL) bsw[BN + i] = bias1[nBase + i];
        }
    }

    // lane-dependent ldmatrix source offsets (bytes within a stage).
    const int lt = lane >> 3, lr = lane & 7;
    const uint32_t aOff = (uint32_t)((wm * WM + (lt & 1) * 8 + lr) * PITCH + (lt >> 1) * 16);
    const uint32_t bOff = (uint32_t)(A_BYTES + (wn * WN + (lt >> 1) * 8 + lr) * PITCH + (lt & 1) * 16);

    auto load_stage = [&](int st, int k0) {   // k0 in halfs
        const uint32_t sb = sBase + st * STAGE;
#pragma unroll
        for (int i = 0; i < ALD; i++) {
            const int ch = tid + i * THREADS;
            const int row = ch >> 2, kc = ch & 3;           // 4 x 16B chunks per row
            cp16(sb + row * PITCH + kc * 16,
                 A + (size_t)(mBase + row) * KDIM + k0 + kc * 8);
        }
#pragma unroll
        for (int i = 0; i < BLD; i++) {
            const int ch = tid + i * THREADS;
            const int row = ch >> 2, kc = ch & 3;
            const size_t g = (size_t)(nBase + row) * KDIM + k0 + kc * 8;
            const uint32_t sa = sb + A_BYTES + row * PITCH + kc * 16;
            cp16(sa, Bt0 + g);
            if constexpr (DUAL) cp16(sa + B_BYTES, Bt1 + g);
        }
    };

    float acc0[MT][NT][4];
    float acc1[DUAL ? MT : 1][DUAL ? NT : 1][4];
#pragma unroll
    for (int mt = 0; mt < MT; mt++)
#pragma unroll
        for (int nt = 0; nt < NT; nt++)
#pragma unroll
            for (int i = 0; i < 4; i++) {
                acc0[mt][nt][i] = 0.0f;
                if constexpr (DUAL) acc1[mt][nt][i] = 0.0f;
            }

#pragma unroll
    for (int st = 0; st < NSTAGE - 1; st++) {
        load_stage(st, st * BK);
        asm volatile("cp.async.commit_group;");
    }

#pragma unroll 1
    for (int kt = 0; kt < KT; kt++) {
        const int cmp_st = kt & (NSTAGE - 1);
        asm volatile("cp.async.wait_group 2;");
        __syncthreads();

        if (kt + NSTAGE - 1 < KT)
            load_stage((kt + NSTAGE - 1) & (NSTAGE - 1), (kt + NSTAGE - 1) * BK);
        asm volatile("cp.async.commit_group;");

        const uint32_t sb = sBase + cmp_st * STAGE;
#pragma unroll
        for (int kk = 0; kk < 2; kk++) {               // 2 x k16 per BK=32 stage
            uint32_t a[MT][4];
#pragma unroll
            for (int mt = 0; mt < MT; mt++)
                ldsm4(a[mt], sb + aOff + mt * 16 * PITCH + kk * 32);

            uint32_t b[NT / 2][4];
#pragma unroll
            for (int np = 0; np < NT / 2; np++)
                ldsm4(b[np], sb + bOff + np * 16 * PITCH + kk * 32);
#pragma unroll
            for (int mt = 0; mt < MT; mt++)
#pragma unroll
                for (int nt = 0; nt < NT; nt++)
                    mma_f16(acc0[mt][nt], a[mt],
                            b[nt >> 1][(nt & 1) * 2], b[nt >> 1][(nt & 1) * 2 + 1]);

            if constexpr (DUAL) {
#pragma unroll
                for (int np = 0; np < NT / 2; np++)
                    ldsm4(b[np], sb + bOff + B_BYTES + np * 16 * PITCH + kk * 32);
#pragma unroll
                for (int mt = 0; mt < MT; mt++)
#pragma unroll
                    for (int nt = 0; nt < NT; nt++)
                        mma_f16(acc1[mt][nt], a[mt],
                                b[nt >> 1][(nt & 1) * 2], b[nt >> 1][(nt & 1) * 2 + 1]);
            }
        }
    }

    // epilogue: c0,c1 at (row g, cols 2t,2t+1); c2,c3 at row g+8
    const float* bsr = reinterpret_cast<const float*>(smem + OFF_BIAS);
    const int r0b = mBase + wm * WM + (lane >> 2);
    const int cbl = wn * WN + (lane & 3) * 2;   // column within block tile
#pragma unroll
    for (int mt = 0; mt < MT; mt++) {
#pragma unroll
        for (int nt = 0; nt < NT; nt++) {
            const int cl = cbl + nt * 8;        // local col
            const int c  = nBase + cl;          // global col
            const int r0 = r0b + mt * 16;
            const int r1 = r0 + 8;
            if constexpr (DUAL) {
                __half* C = reinterpret_cast<__half*>(Cv);
                const float bq0 = bsr[cl], bq1 = bsr[cl + 1];
                const float bv0 = bsr[BN + cl], bv1 = bsr[BN + cl + 1];
                const float g00 = (acc1[mt][nt][0] + bv0) * sigmf(acc0[mt][nt][0] + bq0);
                const float g01 = (acc1[mt][nt][1] + bv1) * sigmf(acc0[mt][nt][1] + bq1);
                const float g10 = (acc1[mt][nt][2] + bv0) * sigmf(acc0[mt][nt][2] + bq0);
                const float g11 = (acc1[mt][nt][3] + bv1) * sigmf(acc0[mt][nt][3] + bq1);
                *reinterpret_cast<__half2*>(C + (size_t)r0 * NDIM + c) =
                    __float22half2_rn(make_float2(g00, g01));
                *reinterpret_cast<__half2*>(C + (size_t)r1 * NDIM + c) =
                    __float22half2_rn(make_float2(g10, g11));
            } else {
                float* C = reinterpret_cast<float*>(Cv);
                const float b0v = bsr[cl], b1v = bsr[cl + 1];
                *reinterpret_cast<float2*>(C + (size_t)r0 * NDIM + c) =
                    make_float2(acc0[mt][nt][0] + b0v, acc0[mt][nt][1] + b1v);
                *reinterpret_cast<float2*>(C + (size_t)r1 * NDIM + c) =
                    make_float2(acc0[mt][nt][2] + b0v, acc0[mt][nt][3] + b1v);
            }
        }
    }
}

// ---------------------------------------------------------------------------
// launch
// ---------------------------------------------------------------------------
extern "C" void kernel_launch(void* const* d_in, const int* in_sizes, int n_in,
                              void* d_out, int out_size) {
    (void)in_sizes; (void)n_in; (void)out_size;
    const float* emb = (const float*)d_in[0];
    const float* Wq  = (const float*)d_in[1];
    const float* bq  = (const float*)d_in[2];
    // d_in[3]=Wk, d_in[4]=bk, d_in[7]=w: algebraically dead (num/den cancels to v)
    const float* Wv  = (const float*)d_in[5];
    const float* bv  = (const float*)d_in[6];
    const float* Wo  = (const float*)d_in[8];
    const float* bo  = (const float*)d_in[9];
    float* out = (float*)d_out;

    __half *embh, *wqt, *wvt, *wot, *mid;
    cudaGetSymbolAddress((void**)&embh, g_emb_h);
    cudaGetSymbolAddress((void**)&wqt,  g_wq_t);
    cudaGetSymbolAddress((void**)&wvt,  g_wv_t);
    cudaGetSymbolAddress((void**)&wot,  g_wo_t);
    cudaGetSymbolAddress((void**)&mid,  g_mid);

    // smem: 4 stages of 20480B + bias block -> 2 CTAs/SM (82944*2 = 166KB)
    constexpr int SMEM = 4 * 20480 + 1024;   // 82944, both variants
    cudaFuncSetAttribute((const void*)gemm_f16<true, 128, 64>,
                         cudaFuncAttributeMaxDynamicSharedMemorySize, SMEM);
    cudaFuncSetAttribute((const void*)gemm_f16<false, 128, 128>,
                         cudaFuncAttributeMaxDynamicSharedMemorySize, SMEM);

    // merged prepass: 1 launch (f2h emb + 3 weight transposes, concurrent)
    prep_kernel<<<7168, 256>>>(emb, Wq, Wv, Wo, embh, wqt, wvt, wot);

    // g = fp16( sigmoid(emb@Wq + bq) * (emb@Wv + bv) )
    dim3 g1(NDIM / 64, M_TOT / 128);   // (16, 64) = 1024 CTAs
    gemm_f16<true, 128, 64><<<g1, 128, SMEM>>>(embh, wqt, wvt, bq, bv, (void*)mid);

    // out = g @ Wo + bo
    dim3 g2(NDIM / 128, M_TOT / 128);  // (8, 64) = 512 CTAs
    gemm_f16<false, 128, 128><<<g2, 128, SMEM>>>(mid, wot, nullptr, bo, nullptr, (void*)out);
}